// round 2
// baseline (speedup 1.0000x reference)
#include <cuda_runtime.h>
#include <math.h>

#define Bsz 256
#define Fseq 256
#define Dh 512
#define NJ3 51
#define IN_DIM 34
#define K0TOT 597   // 34 (x) + 51 (pred) + 512 (h0)
#define K0P 608     // padded
#define K1P 1024    // 512 (h0n) + 512 (h1)

// ---------------- device scratch (statically allocated; no cudaMalloc) ----------------
__device__ float g_W0cat[2048 * K0P];   // folded [embed@Wih0_x^T | Wih0_pred | Whh0]
__device__ float g_bias0[2048];
__device__ float g_W1cat[2048 * K1P];   // [Wih1 | Whh1]
__device__ float g_bias1[2048];
__device__ float g_h0[2][Bsz * Dh];
__device__ float g_h1[2][Bsz * Dh];
__device__ float g_c0[Bsz * Dh];
__device__ float g_c1[Bsz * Dh];
__device__ float g_pred[2][Bsz * 64];   // pred padded to stride 64
__device__ float g_tmp1[Bsz * 512];
__device__ float g_tmp2[Bsz * 1024];
__device__ float g_z[Bsz * 2048];

__device__ __forceinline__ float sigf(float v) { return 1.f / (1.f + expf(-v)); }

// ---------------- one-time weight folding ----------------
__global__ void build_w0_kernel(const float* __restrict__ embed_W,
                                const float* __restrict__ embed_b,
                                const float* __restrict__ Wih0,
                                const float* __restrict__ Whh0,
                                const float* __restrict__ bih0,
                                const float* __restrict__ bhh0) {
    int j = blockIdx.x;            // 0..2047
    int tid = threadIdx.x;         // 128
    for (int k = tid; k < K0P; k += 128) {
        float v = 0.f;
        if (k < IN_DIM) {
            float s = 0.f;
            for (int m = 0; m < 512; m++)
                s += embed_W[k * 512 + m] * Wih0[j * 563 + m];
            v = s;
        } else if (k < IN_DIM + NJ3) {
            v = Wih0[j * 563 + 512 + (k - IN_DIM)];
        } else if (k < K0TOT) {
            v = Whh0[j * 512 + (k - (IN_DIM + NJ3))];
        }
        g_W0cat[j * K0P + k] = v;
    }
    if (tid == 0) {
        float s = bih0[j] + bhh0[j];
        for (int m = 0; m < 512; m++) s += embed_b[m] * Wih0[j * 563 + m];
        g_bias0[j] = s;
    }
}

__global__ void build_w1_kernel(const float* __restrict__ Wih1,
                                const float* __restrict__ Whh1,
                                const float* __restrict__ bih1,
                                const float* __restrict__ bhh1) {
    int j = blockIdx.x;
    int tid = threadIdx.x;  // 256
    for (int k = tid; k < K1P; k += 256) {
        g_W1cat[j * K1P + k] = (k < 512) ? Wih1[j * 512 + k] : Whh1[j * 512 + (k - 512)];
    }
    if (tid == 0) g_bias1[j] = bih1[j] + bhh1[j];
}

// ---------------- generic small GEMM for init net: C = act(A@W + b) ----------------
// A: MxK row-major, W: KxN row-major, C: MxN
__global__ void gemm_bias_act(const float* __restrict__ A, const float* __restrict__ W,
                              const float* __restrict__ bias, float* __restrict__ C,
                              int M, int N, int K, int relu) {
    __shared__ float As[16][17];
    __shared__ float Ws[16][17];
    int tx = threadIdx.x, ty = threadIdx.y;
    int row = blockIdx.y * 16 + ty;
    int col = blockIdx.x * 16 + tx;
    float acc = 0.f;
    for (int k0 = 0; k0 < K; k0 += 16) {
        As[ty][tx] = (row < M && (k0 + tx) < K) ? A[row * K + k0 + tx] : 0.f;
        Ws[ty][tx] = ((k0 + ty) < K && col < N) ? W[(k0 + ty) * N + col] : 0.f;
        __syncthreads();
#pragma unroll
        for (int kk = 0; kk < 16; kk++) acc += As[ty][kk] * Ws[kk][tx];
        __syncthreads();
    }
    if (row < M && col < N) {
        float v = acc + bias[col];
        if (relu) v = fmaxf(v, 0.f);
        C[row * N + col] = v;
    }
}

// ---------------- scatter init-net output into LSTM state ----------------
__global__ void scatter_init_kernel(const float* __restrict__ init) {
    int idx = blockIdx.x * 256 + threadIdx.x;  // 0 .. 131071
    int b = idx >> 9, d = idx & 511;
    const float* zr = g_z + b * 2048;
    g_h0[0][idx] = zr[d];
    g_h1[0][idx] = zr[512 + d];
    g_c0[idx] = zr[1024 + d];
    g_c1[idx] = zr[1536 + d];
    if (d < 64) g_pred[0][b * 64 + d] = (d < NJ3) ? init[b * 85 + d] : 0.f;
}

// ---------------- fused LSTM layer step: GEMM (4 gates) + cell ----------------
// MODE 0: A = [x_t(34) | pred(51) | h0(512)], K=597 (pad 608)
// MODE 1: A = [h0_new(512) | h1(512)], K=1024; also writes ctx into motion_context
template <int MODE>
__global__ void __launch_bounds__(256)
lstm_step_kernel(const float* __restrict__ x, float* __restrict__ out, int t, int par) {
    const int KP = (MODE == 0) ? K0P : K1P;
    const float* __restrict__ W = (MODE == 0) ? g_W0cat : g_W1cat;
    const float* __restrict__ bias = (MODE == 0) ? g_bias0 : g_bias1;
    const float* __restrict__ pred = g_pred[par];
    const float* __restrict__ hin = (MODE == 0) ? g_h0[par] : g_h0[par ^ 1];
    const float* __restrict__ hin2 = g_h1[par];
    float* __restrict__ hout = (MODE == 0) ? g_h0[par ^ 1] : g_h1[par ^ 1];
    float* __restrict__ cst = (MODE == 0) ? g_c0 : g_c1;

    __shared__ __align__(16) float As[16][34];    // [k][b], padded
    __shared__ __align__(16) float Ws[16][130];   // [k][4*32 d], padded

    int tid = threadIdx.x;
    int b0 = blockIdx.x * 32;
    int d0 = blockIdx.y * 32;
    int dd = (tid & 15) * 2;
    int bb = (tid >> 4) * 2;

    float acc[4][2][2];
#pragma unroll
    for (int g = 0; g < 4; g++)
#pragma unroll
        for (int i = 0; i < 2; i++)
#pragma unroll
            for (int j = 0; j < 2; j++) acc[g][i][j] = 0.f;

    for (int kc = 0; kc < KP; kc += 16) {
        // load A tile (512 elems, 2/thread), k fastest for coalescing
#pragma unroll
        for (int i = 0; i < 2; i++) {
            int e = tid + i * 256;
            int bl = e >> 4, k = e & 15;
            int kg = kc + k;
            int b = b0 + bl;
            float v;
            if (MODE == 0) {
                if (kg < IN_DIM)            v = x[(b * Fseq + t) * IN_DIM + kg];
                else if (kg < IN_DIM + NJ3) v = pred[b * 64 + (kg - IN_DIM)];
                else if (kg < K0TOT)        v = hin[b * 512 + (kg - (IN_DIM + NJ3))];
                else                        v = 0.f;
            } else {
                v = (kg < 512) ? hin[b * 512 + kg] : hin2[b * 512 + (kg - 512)];
            }
            As[k][bl] = v;
        }
        // load W tile: 4 gate bands x 32 d x 16 k = 2048 elems, 8/thread
#pragma unroll
        for (int i = 0; i < 8; i++) {
            int e = tid + i * 256;
            int jr = e >> 4, k = e & 15;
            int g = jr >> 5, d = jr & 31;
            Ws[k][jr] = W[(g * 512 + d0 + d) * KP + kc + k];
        }
        __syncthreads();
#pragma unroll
        for (int k = 0; k < 16; k++) {
            float2 a = *(const float2*)&As[k][bb];
#pragma unroll
            for (int g = 0; g < 4; g++) {
                float2 w = *(const float2*)&Ws[k][g * 32 + dd];
                acc[g][0][0] += a.x * w.x;
                acc[g][0][1] += a.x * w.y;
                acc[g][1][0] += a.y * w.x;
                acc[g][1][1] += a.y * w.y;
            }
        }
        __syncthreads();
    }

    // epilogue: bias + LSTM cell (c updated in place, h to ping-pong buffer)
#pragma unroll
    for (int bi = 0; bi < 2; bi++) {
        int b = b0 + bb + bi;
#pragma unroll
        for (int di = 0; di < 2; di++) {
            int d = d0 + dd + di;
            float ig = acc[0][bi][di] + bias[d];
            float fg = acc[1][bi][di] + bias[512 + d];
            float gg = acc[2][bi][di] + bias[1024 + d];
            float og = acc[3][bi][di] + bias[1536 + d];
            float c = cst[b * 512 + d];
            float cn = sigf(fg) * c + sigf(ig) * tanhf(gg);
            float hn = sigf(og) * tanhf(cn);
            cst[b * 512 + d] = cn;
            hout[b * 512 + d] = hn;
            if (MODE == 1) {
                // motion_context[b][t][0:512] = h1_new
                out[(size_t)Bsz * Fseq * NJ3 + ((size_t)b * Fseq + t) * 563 + d] = hn;
            }
        }
    }
}

// ---------------- decode: pred = h1n @ dec_W + dec_b; write outputs ----------------
__global__ void decode_kernel(const float* __restrict__ decW, const float* __restrict__ decb,
                              float* __restrict__ out, int t, int par) {
    int b = blockIdx.x;
    const float* h = g_h1[par ^ 1] + b * 512;
    __shared__ float hs[512];
    for (int i = threadIdx.x; i < 512; i += 64) hs[i] = h[i];
    __syncthreads();
    int n = threadIdx.x;
    if (n < NJ3) {
        float s = decb[n];
#pragma unroll 8
        for (int k = 0; k < 512; k++) s += hs[k] * decW[k * NJ3 + n];
        g_pred[par ^ 1][b * 64 + n] = s;
        size_t bt = (size_t)b * Fseq + t;
        out[bt * NJ3 + n] = s;                                        // pred_kp3d
        out[(size_t)Bsz * Fseq * NJ3 + bt * 563 + 512 + n] = s;       // motion_context tail
    }
}

extern "C" void kernel_launch(void* const* d_in, const int* in_sizes, int n_in,
                              void* d_out, int out_size) {
    const float* x = (const float*)d_in[0];
    const float* init = (const float*)d_in[1];
    const float* embed_W = (const float*)d_in[2];
    const float* embed_b = (const float*)d_in[3];
    const float* ni_W1 = (const float*)d_in[4];
    const float* ni_b1 = (const float*)d_in[5];
    const float* ni_W2 = (const float*)d_in[6];
    const float* ni_b2 = (const float*)d_in[7];
    const float* ni_W3 = (const float*)d_in[8];
    const float* ni_b3 = (const float*)d_in[9];
    const float* Wih0 = (const float*)d_in[10];
    const float* Whh0 = (const float*)d_in[11];
    const float* bih0 = (const float*)d_in[12];
    const float* bhh0 = (const float*)d_in[13];
    const float* Wih1 = (const float*)d_in[14];
    const float* Whh1 = (const float*)d_in[15];
    const float* bih1 = (const float*)d_in[16];
    const float* bhh1 = (const float*)d_in[17];
    const float* dec_W = (const float*)d_in[18];
    const float* dec_b = (const float*)d_in[19];
    float* out = (float*)d_out;

    float *p_tmp1, *p_tmp2, *p_z;
    cudaGetSymbolAddress((void**)&p_tmp1, g_tmp1);
    cudaGetSymbolAddress((void**)&p_tmp2, g_tmp2);
    cudaGetSymbolAddress((void**)&p_z, g_z);

    // one-time (per launch) weight folding
    build_w0_kernel<<<2048, 128>>>(embed_W, embed_b, Wih0, Whh0, bih0, bhh0);
    build_w1_kernel<<<2048, 256>>>(Wih1, Whh1, bih1, bhh1);

    // init net: 85 -> 512 -> 1024 -> 2048
    {
        dim3 blk(16, 16);
        gemm_bias_act<<<dim3(512 / 16, Bsz / 16), blk>>>(init, ni_W1, ni_b1, p_tmp1, Bsz, 512, 85, 1);
        gemm_bias_act<<<dim3(1024 / 16, Bsz / 16), blk>>>(p_tmp1, ni_W2, ni_b2, p_tmp2, Bsz, 1024, 512, 1);
        gemm_bias_act<<<dim3(2048 / 16, Bsz / 16), blk>>>(p_tmp2, ni_W3, ni_b3, p_z, Bsz, 2048, 1024, 0);
    }
    scatter_init_kernel<<<(Bsz * Dh) / 256, 256>>>(init);

    dim3 sgrid(Bsz / 32, Dh / 32);  // 8 x 16 = 128 blocks
    for (int t = 0; t < Fseq; t++) {
        int par = t & 1;
        lstm_step_kernel<0><<<sgrid, 256>>>(x, out, t, par);
        lstm_step_kernel<1><<<sgrid, 256>>>(x, out, t, par);
        decode_kernel<<<Bsz, 64>>>(dec_W, dec_b, out, t, par);
    }
}

// round 3
// speedup vs baseline: 1.0413x; 1.0413x over previous
#include <cuda_runtime.h>
#include <math.h>

#define Bsz 256
#define Fseq 256
#define Dh 512
#define NJ3 51
#define IN_DIM 34
#define K0TOT 597   // 34 (x) + 51 (pred) + 512 (h0)
#define K0P 608     // padded
#define K1P 1024    // 512 (h0n) + 512 (h1)

// ---------------- device scratch (statically allocated; no cudaMalloc) ----------------
__device__ float g_W0cat[2048 * K0P];   // folded [embed@Wih0_x^T | Wih0_pred | Whh0]
__device__ float g_bias0[2048];
__device__ float g_W1cat[2048 * K1P];   // [Wih1 | Whh1]
__device__ float g_bias1[2048];
__device__ float g_h0[2][Bsz * Dh];
__device__ float g_h1[2][Bsz * Dh];
__device__ float g_c0[Bsz * Dh];
__device__ float g_c1[Bsz * Dh];
__device__ float g_pred[2][Bsz * 64];   // pred padded to stride 64
__device__ float g_tmp1[Bsz * 512];
__device__ float g_tmp2[Bsz * 1024];
__device__ float g_z[Bsz * 2048];

__device__ __forceinline__ float sigf(float v) { return 1.f / (1.f + expf(-v)); }

// ---------------- one-time weight folding ----------------
__global__ void build_w0_kernel(const float* __restrict__ embed_W,
                                const float* __restrict__ embed_b,
                                const float* __restrict__ Wih0,
                                const float* __restrict__ Whh0,
                                const float* __restrict__ bih0,
                                const float* __restrict__ bhh0) {
    int j = blockIdx.x;            // 0..2047
    int tid = threadIdx.x;         // 128
    for (int k = tid; k < K0P; k += 128) {
        float v = 0.f;
        if (k < IN_DIM) {
            float s = 0.f;
            for (int m = 0; m < 512; m++)
                s += embed_W[k * 512 + m] * Wih0[j * 563 + m];
            v = s;
        } else if (k < IN_DIM + NJ3) {
            v = Wih0[j * 563 + 512 + (k - IN_DIM)];
        } else if (k < K0TOT) {
            v = Whh0[j * 512 + (k - (IN_DIM + NJ3))];
        }
        g_W0cat[j * K0P + k] = v;
    }
    if (tid == 0) {
        float s = bih0[j] + bhh0[j];
        for (int m = 0; m < 512; m++) s += embed_b[m] * Wih0[j * 563 + m];
        g_bias0[j] = s;
    }
}

__global__ void build_w1_kernel(const float* __restrict__ Wih1,
                                const float* __restrict__ Whh1,
                                const float* __restrict__ bih1,
                                const float* __restrict__ bhh1) {
    int j = blockIdx.x;
    int tid = threadIdx.x;  // 256
    for (int k = tid; k < K1P; k += 256) {
        g_W1cat[j * K1P + k] = (k < 512) ? Wih1[j * 512 + k] : Whh1[j * 512 + (k - 512)];
    }
    if (tid == 0) g_bias1[j] = bih1[j] + bhh1[j];
}

// ---------------- generic small GEMM for init net: C = act(A@W + b) ----------------
// A: MxK row-major, W: KxN row-major, C: MxN
__global__ void gemm_bias_act(const float* __restrict__ A, const float* __restrict__ W,
                              const float* __restrict__ bias, float* __restrict__ C,
                              int M, int N, int K, int relu) {
    __shared__ float As[16][17];
    __shared__ float Ws[16][17];
    int tx = threadIdx.x, ty = threadIdx.y;
    int row = blockIdx.y * 16 + ty;
    int col = blockIdx.x * 16 + tx;
    float acc = 0.f;
    for (int k0 = 0; k0 < K; k0 += 16) {
        As[ty][tx] = (row < M && (k0 + tx) < K) ? A[row * K + k0 + tx] : 0.f;
        Ws[ty][tx] = ((k0 + ty) < K && col < N) ? W[(k0 + ty) * N + col] : 0.f;
        __syncthreads();
#pragma unroll
        for (int kk = 0; kk < 16; kk++) acc += As[ty][kk] * Ws[kk][tx];
        __syncthreads();
    }
    if (row < M && col < N) {
        float v = acc + bias[col];
        if (relu) v = fmaxf(v, 0.f);
        C[row * N + col] = v;
    }
}

// ---------------- scatter init-net output into LSTM state ----------------
__global__ void scatter_init_kernel(const float* __restrict__ init) {
    int idx = blockIdx.x * 256 + threadIdx.x;  // 0 .. 131071
    int b = idx >> 9, d = idx & 511;
    const float* zr = g_z + b * 2048;
    g_h0[0][idx] = zr[d];
    g_h1[0][idx] = zr[512 + d];
    g_c0[idx] = zr[1024 + d];
    g_c1[idx] = zr[1536 + d];
    if (d < 64) g_pred[0][b * 64 + d] = (d < NJ3) ? init[b * 85 + d] : 0.f;
}

// ---------------- fused LSTM layer step: GEMM (4 gates) + cell ----------------
// MODE 0: A = [x_t(34) | pred(51) | h0(512)], K=597 (pad 608)
// MODE 1: A = [h0_new(512) | h1(512)], K=1024; also writes ctx into motion_context
template <int MODE>
__global__ void __launch_bounds__(256)
lstm_step_kernel(const float* __restrict__ x, float* __restrict__ out, int t, int par) {
    const int KP = (MODE == 0) ? K0P : K1P;
    const float* __restrict__ W = (MODE == 0) ? g_W0cat : g_W1cat;
    const float* __restrict__ bias = (MODE == 0) ? g_bias0 : g_bias1;
    const float* __restrict__ pred = g_pred[par];
    const float* __restrict__ hin = (MODE == 0) ? g_h0[par] : g_h0[par ^ 1];
    const float* __restrict__ hin2 = g_h1[par];
    float* __restrict__ hout = (MODE == 0) ? g_h0[par ^ 1] : g_h1[par ^ 1];
    float* __restrict__ cst = (MODE == 0) ? g_c0 : g_c1;

    __shared__ __align__(16) float As[16][34];    // [k][b], padded
    __shared__ __align__(16) float Ws[16][130];   // [k][4*32 d], padded

    int tid = threadIdx.x;
    int b0 = blockIdx.x * 32;
    int d0 = blockIdx.y * 32;
    int dd = (tid & 15) * 2;
    int bb = (tid >> 4) * 2;

    float acc[4][2][2];
#pragma unroll
    for (int g = 0; g < 4; g++)
#pragma unroll
        for (int i = 0; i < 2; i++)
#pragma unroll
            for (int j = 0; j < 2; j++) acc[g][i][j] = 0.f;

    for (int kc = 0; kc < KP; kc += 16) {
        // load A tile (512 elems, 2/thread), k fastest for coalescing
#pragma unroll
        for (int i = 0; i < 2; i++) {
            int e = tid + i * 256;
            int bl = e >> 4, k = e & 15;
            int kg = kc + k;
            int b = b0 + bl;
            float v;
            if (MODE == 0) {
                if (kg < IN_DIM)            v = x[(b * Fseq + t) * IN_DIM + kg];
                else if (kg < IN_DIM + NJ3) v = pred[b * 64 + (kg - IN_DIM)];
                else if (kg < K0TOT)        v = hin[b * 512 + (kg - (IN_DIM + NJ3))];
                else                        v = 0.f;
            } else {
                v = (kg < 512) ? hin[b * 512 + kg] : hin2[b * 512 + (kg - 512)];
            }
            As[k][bl] = v;
        }
        // load W tile: 4 gate bands x 32 d x 16 k = 2048 elems, 8/thread
#pragma unroll
        for (int i = 0; i < 8; i++) {
            int e = tid + i * 256;
            int jr = e >> 4, k = e & 15;
            int g = jr >> 5, d = jr & 31;
            Ws[k][jr] = W[(g * 512 + d0 + d) * KP + kc + k];
        }
        __syncthreads();
#pragma unroll
        for (int k = 0; k < 16; k++) {
            float2 a = *(const float2*)&As[k][bb];
#pragma unroll
            for (int g = 0; g < 4; g++) {
                float2 w = *(const float2*)&Ws[k][g * 32 + dd];
                acc[g][0][0] += a.x * w.x;
                acc[g][0][1] += a.x * w.y;
                acc[g][1][0] += a.y * w.x;
                acc[g][1][1] += a.y * w.y;
            }
        }
        __syncthreads();
    }

    // epilogue: bias + LSTM cell (c updated in place, h to ping-pong buffer)
#pragma unroll
    for (int bi = 0; bi < 2; bi++) {
        int b = b0 + bb + bi;
#pragma unroll
        for (int di = 0; di < 2; di++) {
            int d = d0 + dd + di;
            float ig = acc[0][bi][di] + bias[d];
            float fg = acc[1][bi][di] + bias[512 + d];
            float gg = acc[2][bi][di] + bias[1024 + d];
            float og = acc[3][bi][di] + bias[1536 + d];
            float c = cst[b * 512 + d];
            float cn = sigf(fg) * c + sigf(ig) * tanhf(gg);
            float hn = sigf(og) * tanhf(cn);
            cst[b * 512 + d] = cn;
            hout[b * 512 + d] = hn;
            if (MODE == 1) {
                // motion_context[b][t][0:512] = h1_new
                out[(size_t)Bsz * Fseq * NJ3 + ((size_t)b * Fseq + t) * 563 + d] = hn;
            }
        }
    }
}

// ---------------- decode: pred = h1n @ dec_W + dec_b; write outputs ----------------
__global__ void decode_kernel(const float* __restrict__ decW, const float* __restrict__ decb,
                              float* __restrict__ out, int t, int par) {
    int b = blockIdx.x;
    const float* h = g_h1[par ^ 1] + b * 512;
    __shared__ float hs[512];
    for (int i = threadIdx.x; i < 512; i += 64) hs[i] = h[i];
    __syncthreads();
    int n = threadIdx.x;
    if (n < NJ3) {
        float s = decb[n];
#pragma unroll 8
        for (int k = 0; k < 512; k++) s += hs[k] * decW[k * NJ3 + n];
        g_pred[par ^ 1][b * 64 + n] = s;
        size_t bt = (size_t)b * Fseq + t;
        out[bt * NJ3 + n] = s;                                        // pred_kp3d
        out[(size_t)Bsz * Fseq * NJ3 + bt * 563 + 512 + n] = s;       // motion_context tail
    }
}

extern "C" void kernel_launch(void* const* d_in, const int* in_sizes, int n_in,
                              void* d_out, int out_size) {
    const float* x = (const float*)d_in[0];
    const float* init = (const float*)d_in[1];
    const float* embed_W = (const float*)d_in[2];
    const float* embed_b = (const float*)d_in[3];
    const float* ni_W1 = (const float*)d_in[4];
    const float* ni_b1 = (const float*)d_in[5];
    const float* ni_W2 = (const float*)d_in[6];
    const float* ni_b2 = (const float*)d_in[7];
    const float* ni_W3 = (const float*)d_in[8];
    const float* ni_b3 = (const float*)d_in[9];
    const float* Wih0 = (const float*)d_in[10];
    const float* Whh0 = (const float*)d_in[11];
    const float* bih0 = (const float*)d_in[12];
    const float* bhh0 = (const float*)d_in[13];
    const float* Wih1 = (const float*)d_in[14];
    const float* Whh1 = (const float*)d_in[15];
    const float* bih1 = (const float*)d_in[16];
    const float* bhh1 = (const float*)d_in[17];
    const float* dec_W = (const float*)d_in[18];
    const float* dec_b = (const float*)d_in[19];
    float* out = (float*)d_out;

    float *p_tmp1, *p_tmp2, *p_z;
    cudaGetSymbolAddress((void**)&p_tmp1, g_tmp1);
    cudaGetSymbolAddress((void**)&p_tmp2, g_tmp2);
    cudaGetSymbolAddress((void**)&p_z, g_z);

    // one-time (per launch) weight folding
    build_w0_kernel<<<2048, 128>>>(embed_W, embed_b, Wih0, Whh0, bih0, bhh0);
    build_w1_kernel<<<2048, 256>>>(Wih1, Whh1, bih1, bhh1);

    // init net: 85 -> 512 -> 1024 -> 2048
    {
        dim3 blk(16, 16);
        gemm_bias_act<<<dim3(512 / 16, Bsz / 16), blk>>>(init, ni_W1, ni_b1, p_tmp1, Bsz, 512, 85, 1);
        gemm_bias_act<<<dim3(1024 / 16, Bsz / 16), blk>>>(p_tmp1, ni_W2, ni_b2, p_tmp2, Bsz, 1024, 512, 1);
        gemm_bias_act<<<dim3(2048 / 16, Bsz / 16), blk>>>(p_tmp2, ni_W3, ni_b3, p_z, Bsz, 2048, 1024, 0);
    }
    scatter_init_kernel<<<(Bsz * Dh) / 256, 256>>>(init);

    dim3 sgrid(Bsz / 32, Dh / 32);  // 8 x 16 = 128 blocks
    for (int t = 0; t < Fseq; t++) {
        int par = t & 1;
        lstm_step_kernel<0><<<sgrid, 256>>>(x, out, t, par);
        lstm_step_kernel<1><<<sgrid, 256>>>(x, out, t, par);
        decode_kernel<<<Bsz, 64>>>(dec_W, dec_b, out, t, par);
    }
}